// round 3
// baseline (speedup 1.0000x reference)
#include <cuda_runtime.h>
#include <math.h>

// x (32, 1, 720, 1024) f32 -> out (32, 1, 512, 512) f32
// out[z,y,xp] = (pi/720) * sum_v lerp(x[z,0,v,:], t),  t = xf*cos + yf*sin + 511.5
// t in [150.2, 872.8] for this geometry => always in-bounds.
//
// R2: ZC=2 z-slices per CTA (amortize addressing), duplicated float2 rows in smem
// (one LDS.64 per bilinear tap pair), packed fma.rn.f32x2 accumulate,
// 16x x 2y warp footprint to minimize smem wavefronts.

#define NV  720
#define ND  1024
#define NZ  32
#define NX  512
#define NY  512
#define ZC  2      // z-slices per CTA
#define RYH 8      // y rows per thread (stride 2)

__device__ float g_cos[NV];
__device__ float g_sin[NV];

__global__ void init_trig_kernel() {
    int v = blockIdx.x * blockDim.x + threadIdx.x;
    if (v < NV) {
        float th = (float)v * (float)(M_PI / (double)NV);
        g_cos[v] = cosf(th);
        g_sin[v] = sinf(th);
    }
}

__global__ __launch_bounds__(512, 2) void backproject_kernel(
    const float* __restrict__ x, float* __restrict__ out)
{
    __shared__ float2 dup[2][ZC][ND];        // double-buffered duplicated rows: 32 KB
    __shared__ float s_cos[NV], s_sin[NV];   // 5.76 KB

    const int tid = threadIdx.x;
    const int wrp = tid >> 5;
    const int lx  = tid & 15;          // lane -> 16 x
    const int ly  = (tid >> 4) & 1;    // lane -> 2 y

    for (int i = tid; i < NV; i += 512) { s_cos[i] = g_cos[i]; s_sin[i] = g_sin[i]; }

    const int x0 = blockIdx.x * 256 + wrp * 16 + lx;   // 2 x-tiles of 256
    const int y0 = blockIdx.y * 16 + ly;               // 32 y-tiles of 16
    const int z0 = blockIdx.z * ZC;                    // 16 z-groups of 2

    const float xf = (float)x0 - 255.5f;
    const float yf = (float)y0 - 255.5f;

    // acc[r][z] = (sum (1-w)*g0, sum w*g1) packed f32x2
    unsigned long long acc[RYH][ZC];
#pragma unroll
    for (int r = 0; r < RYH; r++)
#pragma unroll
        for (int zz = 0; zz < ZC; zz++) acc[r][zz] = 0ULL;

    const float* __restrict__ b0 = x + (size_t)(z0 + 0) * (NV * ND);
    const float* __restrict__ b1 = x + (size_t)(z0 + 1) * (NV * ND);

    const int t1 = tid + 1;
    const int t2 = tid + 512;
    const int t3 = (tid + 513 < ND) ? (tid + 513) : (ND - 1);  // clamp (never sampled)

    // Prefetch view 0 rows for both z-slices
    float a0 = b0[tid], a1 = b0[t1], a2 = b0[t2], a3 = b0[t3];
    float c0 = b1[tid], c1 = b1[t1], c2 = b1[t2], c3 = b1[t3];

    for (int v = 0; v < NV; v++) {
        const int buf = v & 1;
        dup[buf][0][tid]       = make_float2(a0, a1);
        dup[buf][0][tid + 512] = make_float2(a2, a3);
        dup[buf][1][tid]       = make_float2(c0, c1);
        dup[buf][1][tid + 512] = make_float2(c2, c3);
        __syncthreads();   // single sync per view; safe with double buffering

        if (v + 1 < NV) {
            const float* __restrict__ n0 = b0 + (size_t)(v + 1) * ND;
            const float* __restrict__ n1 = b1 + (size_t)(v + 1) * ND;
            a0 = n0[tid]; a1 = n0[t1]; a2 = n0[t2]; a3 = n0[t3];
            c0 = n1[tid]; c1 = n1[t1]; c2 = n1[t2]; c3 = n1[t3];
        }

        const float cv = s_cos[v];
        const float sv = s_sin[v];
        float t = fmaf(xf, cv, fmaf(yf, sv, 511.5f));
        const float s2 = sv + sv;   // y stride is 2 rows per r step

#pragma unroll
        for (int r = 0; r < RYH; r++) {
            int   i0 = (int)t;              // t > 0: trunc == floor
            float w  = t - (float)i0;
            float w0 = 1.0f - w;
            unsigned long long w2;
            asm("mov.b64 %0, {%1, %2};" : "=l"(w2) : "f"(w0), "f"(w));
            unsigned long long h0 = *reinterpret_cast<const unsigned long long*>(&dup[buf][0][i0]);
            unsigned long long h1 = *reinterpret_cast<const unsigned long long*>(&dup[buf][1][i0]);
            asm("fma.rn.f32x2 %0, %1, %2, %0;" : "+l"(acc[r][0]) : "l"(w2), "l"(h0));
            asm("fma.rn.f32x2 %0, %1, %2, %0;" : "+l"(acc[r][1]) : "l"(w2), "l"(h1));
            t += s2;
        }
    }

    const float scale = (float)(M_PI / (double)NV);
#pragma unroll
    for (int r = 0; r < RYH; r++) {
#pragma unroll
        for (int zz = 0; zz < ZC; zz++) {
            float lo, hi;
            asm("mov.b64 {%0, %1}, %2;" : "=f"(lo), "=f"(hi) : "l"(acc[r][zz]));
            out[((size_t)(z0 + zz) * NY + (y0 + 2 * r)) * NX + x0] = (lo + hi) * scale;
        }
    }
}

extern "C" void kernel_launch(void* const* d_in, const int* in_sizes, int n_in,
                              void* d_out, int out_size)
{
    const float* x   = (const float*)d_in[0];
    float*       out = (float*)d_out;

    init_trig_kernel<<<(NV + 255) / 256, 256>>>();

    dim3 grid(2, 32, 16);   // x-tiles, y-tiles, z-groups = 1024 CTAs
    backproject_kernel<<<grid, 512>>>(x, out);
}

// round 4
// speedup vs baseline: 1.6125x; 1.6125x over previous
#include <cuda_runtime.h>
#include <math.h>

// x (32, 1, 720, 1024) f32 -> out (32, 1, 512, 512) f32
// out[z,y,xp] = (pi/720) * sum_v lerp(x[z,0,v,:], t),  t = xf*cos + yf*sin + 511.5
// t in [150.2, 872.8] => always in-bounds for nDct=1024.
//
// R3: z-quad float4 detector cells (1 LDS.128 tap serves 4 z-samples),
// windowed staging (only the ~75 cells a 64x x 32y tile can touch per view),
// 8x x 4y warp footprint for minimal smem spans, f32x2 packed accumulate.

#define NV   720
#define ND   1024
#define NVND (NV * ND)
#define NZ   32
#define NXI  512
#define NYI  512
#define WIN  96     // staged window cells per view (max needed ~75 + slack)
#define RY   8      // r-steps per thread (y stride 4)

__device__ float g_cos[NV];
__device__ float g_sin[NV];

__global__ void init_trig_kernel() {
    int v = blockIdx.x * blockDim.x + threadIdx.x;
    if (v < NV) {
        float th = (float)v * (float)(M_PI / (double)NV);
        g_cos[v] = cosf(th);
        g_sin[v] = sinf(th);
    }
}

// dmin must be computed identically by stager and consumers (it is: same FP ops).
__device__ __forceinline__ int calc_dmin(float c, float s, float xfmin, float yf0) {
    float xsel = (c >= 0.0f) ? xfmin : (xfmin + 63.0f);
    float tmin = fmaf(xsel, c, fmaf(yf0, s, 511.5f));   // s >= 0 on [0,pi)
    return (int)tmin - 1;                               // tmin > 0: trunc==floor; -1 = ulp safety
}

__global__ __launch_bounds__(256, 4) void backproject_kernel(
    const float* __restrict__ x, float* __restrict__ out)
{
    __shared__ float4 cell[2][WIN];          // z-quad interleaved window, double-buffered (3 KB)
    __shared__ float s_cos[NV], s_sin[NV];   // 5.76 KB

    const int tid  = threadIdx.x;            // 256 threads = 8 warps
    const int lane = tid & 31;
    const int wrp  = tid >> 5;
    const int lx   = lane & 7;               // 8 x per warp
    const int ly   = lane >> 3;              // 4 y per warp

    for (int i = tid; i < NV; i += 256) { s_cos[i] = g_cos[i]; s_sin[i] = g_sin[i]; }

    const int xg = blockIdx.x * 64 + wrp * 8 + lx;   // 8 x-tiles of 64
    const int yb = blockIdx.y * 32 + ly;             // 16 y-tiles of 32; thread rows yb + 4r
    const int zq = blockIdx.z * 4;                   // 8 z-quads

    const float xf    = (float)xg - 255.5f;
    const float ybf   = (float)yb - 255.5f;
    const float xfmin = (float)(blockIdx.x * 64) - 255.5f;
    const float yf0   = (float)(blockIdx.y * 32) - 255.5f;

    // acc[r][p]: f32x2 lanes = (z_{2p}, z_{2p+1}) running sums
    unsigned long long acc[RY][2];
#pragma unroll
    for (int r = 0; r < RY; r++) { acc[r][0] = 0ULL; acc[r][1] = 0ULL; }

    const float* __restrict__ gz = x + (size_t)zq * NVND;   // z-quad base

    // shared-window base as 32-bit shared address for asm LDS
    unsigned int cell_base;
    asm("{ .reg .u64 t; cvta.to.shared.u64 t, %1; cvt.u32.u64 %0, t; }"
        : "=r"(cell_base) : "l"((const void*)cell));

    // Prefetch view 0 window (theta=0: c=1, s=0 exactly)
    float r0 = 0.f, r1 = 0.f, r2 = 0.f, r3 = 0.f;
    if (tid < WIN) {
        int dm = calc_dmin(1.0f, 0.0f, xfmin, yf0);
        const float* g = gz + dm + tid;          // view 0 row offset = 0
        r0 = g[0]; r1 = g[NVND]; r2 = g[2 * NVND]; r3 = g[3 * NVND];
    }

    for (int v = 0; v < NV; v++) {
        const int buf = v & 1;
        if (tid < WIN) cell[buf][tid] = make_float4(r0, r1, r2, r3);
        __syncthreads();   // single sync per view; double buffering covers WAR

        if (v + 1 < NV && tid < WIN) {
            float c1 = s_cos[v + 1], s1 = s_sin[v + 1];
            int dm = calc_dmin(c1, s1, xfmin, yf0);
            const float* g = gz + (size_t)(v + 1) * ND + dm + tid;
            r0 = g[0]; r1 = g[NVND]; r2 = g[2 * NVND]; r3 = g[3 * NVND];
        }

        const float c = s_cos[v];
        const float s = s_sin[v];
        const int dmin = calc_dmin(c, s, xfmin, yf0);
        // u = t - dmin, guaranteed in [0, WIN-2) for this tile's pixels
        float u = fmaf(xf, c, fmaf(ybf, s, 511.5f - (float)dmin));
        const float s4 = 4.0f * s;                 // y stride 4 rows per r-step
        const unsigned int base = cell_base + (buf ? (unsigned)(WIN * 16) : 0u);

#pragma unroll
        for (int r = 0; r < RY; r++) {
            int   i0 = (int)u;                     // u > 0: trunc == floor
            float w  = u - (float)i0;
            float w0 = 1.0f - w;
            unsigned long long w02, w2;
            asm("mov.b64 %0, {%1, %1};" : "=l"(w02) : "f"(w0));
            asm("mov.b64 %0, {%1, %1};" : "=l"(w2)  : "f"(w));
            unsigned int a0 = base + (unsigned)i0 * 16u;
            unsigned long long h0a, h0b, h1a, h1b;
            asm("ld.shared.v2.b64 {%0, %1}, [%2];"      : "=l"(h0a), "=l"(h0b) : "r"(a0));
            asm("ld.shared.v2.b64 {%0, %1}, [%2 + 16];" : "=l"(h1a), "=l"(h1b) : "r"(a0));
            asm("fma.rn.f32x2 %0, %1, %2, %0;" : "+l"(acc[r][0]) : "l"(w02), "l"(h0a));
            asm("fma.rn.f32x2 %0, %1, %2, %0;" : "+l"(acc[r][0]) : "l"(w2),  "l"(h1a));
            asm("fma.rn.f32x2 %0, %1, %2, %0;" : "+l"(acc[r][1]) : "l"(w02), "l"(h0b));
            asm("fma.rn.f32x2 %0, %1, %2, %0;" : "+l"(acc[r][1]) : "l"(w2),  "l"(h1b));
            u += s4;
        }
    }

    const float scale = (float)(M_PI / (double)NV);
#pragma unroll
    for (int r = 0; r < RY; r++) {
        const int y = yb + 4 * r;
#pragma unroll
        for (int p = 0; p < 2; p++) {
            float lo, hi;
            asm("mov.b64 {%0, %1}, %2;" : "=f"(lo), "=f"(hi) : "l"(acc[r][p]));
            out[((size_t)(zq + 2 * p)     * NYI + y) * NXI + xg] = lo * scale;
            out[((size_t)(zq + 2 * p + 1) * NYI + y) * NXI + xg] = hi * scale;
        }
    }
}

extern "C" void kernel_launch(void* const* d_in, const int* in_sizes, int n_in,
                              void* d_out, int out_size)
{
    const float* x   = (const float*)d_in[0];
    float*       out = (float*)d_out;

    init_trig_kernel<<<(NV + 255) / 256, 256>>>();

    dim3 grid(8, 16, 8);   // x-tiles, y-tiles, z-quads = 1024 CTAs
    backproject_kernel<<<grid, 256>>>(x, out);
}

// round 5
// speedup vs baseline: 1.6687x; 1.0348x over previous
#include <cuda_runtime.h>
#include <cuda_fp16.h>
#include <math.h>

// x (32, 1, 720, 1024) f32 -> out (32, 1, 512, 512) f32
// out[z,y,xp] = (pi/720) * sum_v lerp(x[z,0,v,:], t),  t = xf*cos + yf*sin + 511.5
// t in [150.2, 872.8] => always in-bounds for nDct=1024.
//
// R4: fp16 z-oct detector cells (16 B = 8 z). Two LDS.128 taps serve 8 z-samples
// (4 B/sample smem read vs fp32's 8 -> halves the crossbar-phase floor).
// f32 accumulation (precision kept), windowed staging of 80 cells/view,
// scalar overhead amortized over 8 z.

#define NV   720
#define ND   1024
#define NVND (NV * ND)
#define NXI  512
#define NYI  512
#define WIN  80     // staged window cells per view (max span ~67 + slack)
#define RY   4      // r-steps per thread (y stride 4) -> 16 y rows per warp
#define ZC   8      // z-slices per cell

__device__ float g_cos[NV];
__device__ float g_sin[NV];

__global__ void init_trig_kernel() {
    int v = blockIdx.x * blockDim.x + threadIdx.x;
    if (v < NV) {
        float th = (float)v * (float)(M_PI / (double)NV);
        g_cos[v] = cosf(th);
        g_sin[v] = sinf(th);
    }
}

// Must be computed identically by stager and consumers (same FP ops => it is).
__device__ __forceinline__ int calc_dmin(float c, float s, float xfmin, float yf0) {
    float xsel = (c >= 0.0f) ? xfmin : (xfmin + 63.0f);   // 64-wide x tile
    float tmin = fmaf(xsel, c, fmaf(yf0, s, 511.5f));     // s >= 0 on [0,pi)
    return (int)tmin - 1;                                 // tmin > 0: trunc==floor; -1 ulp guard
}

__global__ __launch_bounds__(256, 3) void backproject_kernel(
    const float* __restrict__ x, float* __restrict__ out)
{
    __shared__ uint4 cell[2][WIN];           // half8 z-oct cells, double-buffered (2.5 KB)
    __shared__ float s_cos[NV], s_sin[NV];   // 5.76 KB

    const int tid  = threadIdx.x;            // 256 threads = 8 warps
    const int lane = tid & 31;
    const int wrp  = tid >> 5;
    const int lx   = lane & 7;               // 8 x per warp
    const int ly   = lane >> 3;              // 4 y per warp

    for (int i = tid; i < NV; i += 256) { s_cos[i] = g_cos[i]; s_sin[i] = g_sin[i]; }

    const int xg = blockIdx.x * 64 + wrp * 8 + lx;   // 8 x-tiles of 64
    const int yb = blockIdx.y * 16 + ly;             // 32 y-tiles of 16; thread rows yb + 4r
    const int zq = blockIdx.z * ZC;                  // 4 z-octs

    const float xf    = (float)xg - 255.5f;
    const float ybf   = (float)yb - 255.5f;
    const float xfmin = (float)(blockIdx.x * 64) - 255.5f;
    const float yf0   = (float)(blockIdx.y * 16) - 255.5f;

    float acc[RY][ZC];
#pragma unroll
    for (int r = 0; r < RY; r++)
#pragma unroll
        for (int zz = 0; zz < ZC; zz++) acc[r][zz] = 0.0f;

    // shared-window base as 32-bit shared address for asm LDS
    unsigned int cell_base;
    asm("{ .reg .u64 t; cvta.to.shared.u64 t, %1; cvt.u32.u64 %0, t; }"
        : "=r"(cell_base) : "l"((const void*)cell));

    // Staging role: 160 threads, each owns (cell c, z-half zh) -> 4 z values.
    const int st_on = (tid < 160);
    const int zh    = (tid >= 80) ? 1 : 0;
    const int sc    = tid - zh * 80;              // cell index 0..79
    const float* __restrict__ gsl = x + (size_t)(zq + zh * 4) * NVND;

    // Prefetch view 0 window (theta=0: c=1, s=0 exactly)
    float r0 = 0.f, r1 = 0.f, r2 = 0.f, r3 = 0.f;
    if (st_on) {
        int dm = calc_dmin(1.0f, 0.0f, xfmin, yf0);
        const float* g = gsl + dm + sc;           // view 0 row offset = 0
        r0 = g[0]; r1 = g[NVND]; r2 = g[2 * NVND]; r3 = g[3 * NVND];
    }

    for (int v = 0; v < NV; v++) {
        const int buf = v & 1;
        if (st_on) {
            __half2 h01 = __floats2half2_rn(r0, r1);
            __half2 h23 = __floats2half2_rn(r2, r3);
            unsigned u01 = *reinterpret_cast<unsigned*>(&h01);
            unsigned u23 = *reinterpret_cast<unsigned*>(&h23);
            *reinterpret_cast<uint2*>(
                reinterpret_cast<unsigned*>(&cell[buf][sc]) + zh * 2) = make_uint2(u01, u23);
        }
        __syncthreads();   // single sync per view; double buffering covers WAR

        if (v + 1 < NV && st_on) {
            float c1 = s_cos[v + 1], s1 = s_sin[v + 1];
            int dm = calc_dmin(c1, s1, xfmin, yf0);
            const float* g = gsl + (size_t)(v + 1) * ND + dm + sc;
            r0 = g[0]; r1 = g[NVND]; r2 = g[2 * NVND]; r3 = g[3 * NVND];
        }

        const float c = s_cos[v];
        const float s = s_sin[v];
        const int dmin = calc_dmin(c, s, xfmin, yf0);
        // u = t - dmin, in [0, WIN-2) for every pixel of this tile
        float u = fmaf(xf, c, fmaf(ybf, s, 511.5f - (float)dmin));
        const float s4 = 4.0f * s;                 // y stride 4 rows per r-step
        const unsigned int base = cell_base + (buf ? (unsigned)(WIN * 16) : 0u);

#pragma unroll
        for (int r = 0; r < RY; r++) {
            int   i0 = (int)u;                     // u > 0: trunc == floor
            float w  = u - (float)i0;
            float w0 = 1.0f - w;
            unsigned int a0 = base + (unsigned)i0 * 16u;
            uint4 A, B;
            asm("ld.shared.v4.b32 {%0,%1,%2,%3}, [%4];"
                : "=r"(A.x), "=r"(A.y), "=r"(A.z), "=r"(A.w) : "r"(a0));
            asm("ld.shared.v4.b32 {%0,%1,%2,%3}, [%4 + 16];"
                : "=r"(B.x), "=r"(B.y), "=r"(B.z), "=r"(B.w) : "r"(a0));
#pragma unroll
            for (int p = 0; p < 4; p++) {
                unsigned ua = (p == 0) ? A.x : (p == 1) ? A.y : (p == 2) ? A.z : A.w;
                unsigned ub = (p == 0) ? B.x : (p == 1) ? B.y : (p == 2) ? B.z : B.w;
                float2 fa = __half22float2(*reinterpret_cast<__half2*>(&ua));
                float2 fb = __half22float2(*reinterpret_cast<__half2*>(&ub));
                acc[r][2 * p]     = fmaf(w0, fa.x, acc[r][2 * p]);
                acc[r][2 * p]     = fmaf(w,  fb.x, acc[r][2 * p]);
                acc[r][2 * p + 1] = fmaf(w0, fa.y, acc[r][2 * p + 1]);
                acc[r][2 * p + 1] = fmaf(w,  fb.y, acc[r][2 * p + 1]);
            }
            u += s4;
        }
    }

    const float scale = (float)(M_PI / (double)NV);
#pragma unroll
    for (int r = 0; r < RY; r++) {
        const int y = yb + 4 * r;
#pragma unroll
        for (int zz = 0; zz < ZC; zz++) {
            out[((size_t)(zq + zz) * NYI + y) * NXI + xg] = acc[r][zz] * scale;
        }
    }
}

extern "C" void kernel_launch(void* const* d_in, const int* in_sizes, int n_in,
                              void* d_out, int out_size)
{
    const float* x   = (const float*)d_in[0];
    float*       out = (float*)d_out;

    init_trig_kernel<<<(NV + 255) / 256, 256>>>();

    dim3 grid(8, 32, 4);   // x-tiles, y-tiles, z-octs = 1024 CTAs
    backproject_kernel<<<grid, 256>>>(x, out);
}